// round 1
// baseline (speedup 1.0000x reference)
#include <cuda_runtime.h>
#include <math.h>

#define BS   16
#define CIN  256
#define COUT 256
#define HH   80
#define WW   80
#define HWSZ 6400
#define HID  16
#define KNUM 5

// ---------------- scratch (static device globals; no allocation) ----------------
__device__ float g_pooled[BS * CIN];
__device__ float g_mix[BS * 9 * 9];          // [b][cd][s]
__device__ float g_cinatt[BS * CIN];
__device__ float g_outatt[BS * COUT];
__device__ float g_aggb[BS * COUT];
__device__ float g_W[(size_t)BS * CIN * 9 * COUT];   // [b][i][tap][o], 37.7 MB

// rotation perms: dest -> source flat index (k=0 identity, then 45/90/135/180)
__constant__ int c_perm[KNUM][9] = {
    {0,1,2,3,4,5,6,7,8},
    {3,0,1,6,4,2,7,8,5},
    {6,3,0,7,4,1,8,5,2},
    {7,6,3,8,4,0,5,2,1},
    {8,7,6,5,4,3,2,1,0},
};

__device__ __forceinline__ float sigmoidf_(float z) { return 1.f / (1.f + expf(-z)); }

// ---------------- kernel 1: global average pool ----------------
__global__ void pool_kernel(const float* __restrict__ x)
{
    int bc = blockIdx.x;                      // b*CIN + i
    const float* p = x + (size_t)bc * HWSZ;
    int tid = threadIdx.x;
    float s = 0.f;
    for (int i = tid; i < HWSZ; i += 256) s += p[i];
    __shared__ float sred[256];
    sred[tid] = s;
    __syncthreads();
    for (int st = 128; st > 0; st >>= 1) {
        if (tid < st) sred[tid] += sred[tid + st];
        __syncthreads();
    }
    if (tid == 0) g_pooled[bc] = sred[0] * (1.f / (float)HWSZ);
}

// ---------------- kernel 2: attention heads + mix coefficients + bias ----------------
__global__ void att_kernel(const float* __restrict__ w_net,
                           const float* __restrict__ w_nfc,
                           const float* __restrict__ w_cin,
                           const float* __restrict__ w_k2,
                           const float* __restrict__ w_out,
                           const float* __restrict__ b_base,
                           const float* __restrict__ b_extra)
{
    __shared__ float h_s[BS][HID];
    __shared__ float natt_s[BS][KNUM];
    __shared__ float k2_s[BS][9];
    int t = threadIdx.x;

    // h = relu(pooled @ w_net^T): 16x16 = 256 threads, one dot each
    {
        int b = t >> 4, j = t & 15;
        const float* pr = &g_pooled[b * CIN];
        const float* wr = &w_net[j * CIN];
        float s = 0.f;
        for (int i = 0; i < CIN; ++i) s += pr[i] * wr[i];
        h_s[b][j] = fmaxf(s, 0.f);
    }
    __syncthreads();

    // softmax over K with temperature
    if (t < BS) {
        float l[KNUM];
        float mx = -1e30f;
        for (int k = 0; k < KNUM; ++k) {
            float s = 0.f;
            for (int j = 0; j < HID; ++j) s += h_s[t][j] * w_nfc[k * HID + j];
            l[k] = s * (1.f / 30.f);
            mx = fmaxf(mx, l[k]);
        }
        float den = 0.f;
        for (int k = 0; k < KNUM; ++k) { l[k] = expf(l[k] - mx); den += l[k]; }
        float inv = 1.f / den;
        for (int k = 0; k < KNUM; ++k) natt_s[t][k] = l[k] * inv;
    }
    // k2 attention (9 per sample)
    if (t >= 64 && t < 64 + BS * 9) {
        int idx = t - 64;
        int b = idx / 9, cd = idx % 9;
        float s = 0.f;
        for (int j = 0; j < HID; ++j) s += h_s[b][j] * w_k2[cd * HID + j];
        k2_s[b][cd] = sigmoidf_(s);
    }
    __syncthreads();

    // mix[b][cd][s] = k2[b][cd] * sum_k natt[b][k] * [perm_k[cd] == s]
    if (t < BS * 9) {
        int b = t / 9, cd = t % 9;
        float m[9];
#pragma unroll
        for (int s = 0; s < 9; ++s) m[s] = 0.f;
#pragma unroll
        for (int k = 0; k < KNUM; ++k) m[c_perm[k][cd]] += natt_s[b][k];
        float k2v = k2_s[b][cd];
#pragma unroll
        for (int s = 0; s < 9; ++s) g_mix[(b * 9 + cd) * 9 + s] = k2v * m[s];
    }

    // cin_att / out_att / aggregated bias
    for (int idx = t; idx < BS * CIN; idx += blockDim.x) {
        int b = idx >> 8, c = idx & 255;
        float s1 = 0.f, s2 = 0.f;
        for (int j = 0; j < HID; ++j) {
            float hv = h_s[b][j];
            s1 += hv * w_cin[c * HID + j];
            s2 += hv * w_out[c * HID + j];
        }
        g_cinatt[idx] = sigmoidf_(s1);
        g_outatt[idx] = sigmoidf_(s2);
        float bb = natt_s[b][0] * b_base[c];
        for (int k = 1; k < KNUM; ++k) bb += natt_s[b][k] * b_extra[(k - 1) * COUT + c];
        g_aggb[idx] = bb;
    }
}

// ---------------- kernel 3: materialize fused per-sample weights ----------------
// g_W[b][i][tap][o] = cin[b][i]*out[b][o] * sum_s mix[b][tap][s] * w_base[o][i][s]
__global__ void wfuse_kernel(const float* __restrict__ w_base)
{
    int i = blockIdx.x;
    int b = blockIdx.y;
    int o = threadIdx.x;
    __shared__ float mix_s[81];
    if (o < 81) mix_s[o] = g_mix[b * 81 + o];
    __syncthreads();

    float wb[9];
    const float* wp = &w_base[((size_t)o * CIN + i) * 9];
#pragma unroll
    for (int s = 0; s < 9; ++s) wb[s] = wp[s];
    float sc = g_cinatt[b * CIN + i] * g_outatt[b * COUT + o];
    float* dst = &g_W[(((size_t)(b * CIN + i)) * 9) * COUT + o];
#pragma unroll
    for (int tt = 0; tt < 9; ++tt) {
        float v = 0.f;
#pragma unroll
        for (int s = 0; s < 9; ++s) v += mix_s[tt * 9 + s] * wb[s];
        dst[(size_t)tt * COUT] = sc * v;
    }
}

// ---------------- packed f32x2 helpers ----------------
__device__ __forceinline__ unsigned long long ffma2(unsigned long long a,
                                                    unsigned long long b,
                                                    unsigned long long c)
{
    unsigned long long d;
    asm("fma.rn.f32x2 %0, %1, %2, %3;" : "=l"(d) : "l"(a), "l"(b), "l"(c));
    return d;
}
__device__ __forceinline__ unsigned long long bcast2(float x)
{
    unsigned long long d;
    unsigned u = __float_as_uint(x);
    asm("mov.b64 %0, {%1, %2};" : "=l"(d) : "r"(u), "r"(u));
    return d;
}

// ---------------- kernel 4: per-sample 3x3 conv (implicit GEMM, f32x2) ----------------
// CTA: sample b, 64 output channels, 16x16 spatial tile.
// Thread: 16 output channels (8 packed pairs) x 4 consecutive width positions.
#define BKC 8
__global__ __launch_bounds__(256, 2) void conv_kernel(const float* __restrict__ x,
                                                      float* __restrict__ out)
{
    const int b   = blockIdx.z;
    const int ocb = blockIdx.y;                 // 0..3 -> 64-channel block
    const int th0 = (blockIdx.x / 5) * 16;
    const int tw0 = (blockIdx.x % 5) * 16;
    const int tid = threadIdx.x;
    const int g   = tid >> 6;                   // 0..3 -> 16-channel sub block
    const int p   = tid & 63;
    const int row = p >> 2;                     // 0..15
    const int cg  = (p & 3) << 2;               // 0,4,8,12

    __shared__ float xs[BKC][18][20];           // halo tile, padded rows
    __shared__ float ws[BKC][9][64];            // [kc][tap][oc]

    unsigned long long acc[8][4];
#pragma unroll
    for (int q = 0; q < 8; ++q)
#pragma unroll
        for (int pos = 0; pos < 4; ++pos) acc[q][pos] = 0ULL;

    const float* xb  = x + (size_t)b * CIN * HWSZ;
    const float* wbp = g_W + (size_t)b * CIN * 9 * COUT + (size_t)ocb * 64;

    for (int kc0 = 0; kc0 < CIN; kc0 += BKC) {
        __syncthreads();
        // stage x halo tile (zero-padded borders)
#pragma unroll 1
        for (int idx = tid; idx < BKC * 18 * 18; idx += 256) {
            int kc = idx / 324;
            int rem = idx - kc * 324;
            int r = rem / 18;
            int c = rem - r * 18;
            int gh = th0 - 1 + r, gw = tw0 - 1 + c;
            float v = 0.f;
            if ((unsigned)gh < 80u && (unsigned)gw < 80u)
                v = __ldg(&xb[(size_t)(kc0 + kc) * HWSZ + gh * 80 + gw]);
            xs[kc][r][c] = v;
        }
        // stage weights
#pragma unroll 1
        for (int idx = tid; idx < BKC * 9 * 64; idx += 256) {
            int kc = idx / 576;
            int rem = idx - kc * 576;
            int tt = rem >> 6;
            int oc = rem & 63;
            ws[kc][tt][oc] = wbp[(size_t)((kc0 + kc) * 9 + tt) * COUT + oc];
        }
        __syncthreads();

#pragma unroll 2
        for (int kc = 0; kc < BKC; ++kc) {
#pragma unroll
            for (int tr = 0; tr < 3; ++tr) {
                const float* xp = &xs[kc][row + tr][cg];
                float4 v4 = *reinterpret_cast<const float4*>(xp);
                float2 v2 = *reinterpret_cast<const float2*>(xp + 4);
                unsigned long long xx[6];
                xx[0] = bcast2(v4.x); xx[1] = bcast2(v4.y); xx[2] = bcast2(v4.z);
                xx[3] = bcast2(v4.w); xx[4] = bcast2(v2.x); xx[5] = bcast2(v2.y);
#pragma unroll
                for (int tc = 0; tc < 3; ++tc) {
                    const unsigned long long* wp2 =
                        reinterpret_cast<const unsigned long long*>(&ws[kc][tr * 3 + tc][g * 16]);
#pragma unroll
                    for (int q = 0; q < 8; ++q) {
                        unsigned long long w2 = wp2[q];
                        acc[q][0] = ffma2(w2, xx[tc + 0], acc[q][0]);
                        acc[q][1] = ffma2(w2, xx[tc + 1], acc[q][1]);
                        acc[q][2] = ffma2(w2, xx[tc + 2], acc[q][2]);
                        acc[q][3] = ffma2(w2, xx[tc + 3], acc[q][3]);
                    }
                }
            }
        }
    }

    // epilogue: unpack, add aggregated bias, vectorized stores
    const int oc_base = ocb * 64 + g * 16;
    const int hh = th0 + row;
    const int wc = tw0 + cg;
#pragma unroll
    for (int q = 0; q < 8; ++q) {
        int oc_lo = oc_base + 2 * q;
        float blo = g_aggb[b * COUT + oc_lo];
        float bhi = g_aggb[b * COUT + oc_lo + 1];
        float lo[4], hi[4];
#pragma unroll
        for (int pos = 0; pos < 4; ++pos) {
            unsigned l32, h32;
            asm("mov.b64 {%0, %1}, %2;" : "=r"(l32), "=r"(h32) : "l"(acc[q][pos]));
            lo[pos] = __uint_as_float(l32) + blo;
            hi[pos] = __uint_as_float(h32) + bhi;
        }
        float* olo = out + (((size_t)b * COUT + oc_lo) * HH + hh) * WW + wc;
        float* ohi = olo + HWSZ;
        *reinterpret_cast<float4*>(olo) = make_float4(lo[0], lo[1], lo[2], lo[3]);
        *reinterpret_cast<float4*>(ohi) = make_float4(hi[0], hi[1], hi[2], hi[3]);
    }
}

// ---------------- launch ----------------
extern "C" void kernel_launch(void* const* d_in, const int* in_sizes, int n_in,
                              void* d_out, int out_size)
{
    const float* x       = (const float*)d_in[0];
    const float* w_base  = (const float*)d_in[1];
    const float* b_base  = (const float*)d_in[2];
    const float* b_extra = (const float*)d_in[3];
    const float* w_net   = (const float*)d_in[4];
    const float* w_nfc   = (const float*)d_in[5];
    const float* w_cin   = (const float*)d_in[6];
    const float* w_k2    = (const float*)d_in[7];
    const float* w_out   = (const float*)d_in[8];
    float* out = (float*)d_out;

    pool_kernel<<<BS * CIN, 256>>>(x);
    att_kernel<<<1, 256>>>(w_net, w_nfc, w_cin, w_k2, w_out, b_base, b_extra);
    {
        dim3 grid(CIN, BS);
        wfuse_kernel<<<grid, 256>>>(w_base);
    }
    {
        dim3 grid(25, 4, BS);
        conv_kernel<<<grid, 256>>>(x, out);
    }
}

// round 2
// speedup vs baseline: 1.4425x; 1.4425x over previous
#include <cuda_runtime.h>
#include <math.h>

#define BS   16
#define CIN  256
#define COUT 256
#define HH   80
#define WW   80
#define HWSZ 6400
#define HID  16
#define KNUM 5

// ---------------- scratch (static device globals; no allocation) ----------------
__device__ float g_pooled[BS * CIN];
__device__ float g_mix[BS * 9 * 9];          // [b][cd][s]
__device__ float g_cinatt[BS * CIN];
__device__ float g_outatt[BS * COUT];
__device__ float g_aggb[BS * COUT];
__device__ __align__(16) float g_W[(size_t)BS * CIN * 9 * COUT];   // [b][i][tap][o]

// rotation perms: dest -> source flat index (k=0 identity, then 45/90/135/180)
__constant__ int c_perm[KNUM][9] = {
    {0,1,2,3,4,5,6,7,8},
    {3,0,1,6,4,2,7,8,5},
    {6,3,0,7,4,1,8,5,2},
    {7,6,3,8,4,0,5,2,1},
    {8,7,6,5,4,3,2,1,0},
};

__device__ __forceinline__ float sigmoidf_(float z) { return 1.f / (1.f + expf(-z)); }

// ---------------- kernel 1: global average pool ----------------
__global__ void pool_kernel(const float* __restrict__ x)
{
    int bc = blockIdx.x;                      // b*CIN + i
    const float* p = x + (size_t)bc * HWSZ;
    int tid = threadIdx.x;
    float s = 0.f;
    for (int i = tid; i < HWSZ; i += 256) s += p[i];
    __shared__ float sred[256];
    sred[tid] = s;
    __syncthreads();
    for (int st = 128; st > 0; st >>= 1) {
        if (tid < st) sred[tid] += sred[tid + st];
        __syncthreads();
    }
    if (tid == 0) g_pooled[bc] = sred[0] * (1.f / (float)HWSZ);
}

// ---------------- kernel 2: attention heads + mix coefficients + bias ----------------
__global__ void att_kernel(const float* __restrict__ w_net,
                           const float* __restrict__ w_nfc,
                           const float* __restrict__ w_cin,
                           const float* __restrict__ w_k2,
                           const float* __restrict__ w_out,
                           const float* __restrict__ b_base,
                           const float* __restrict__ b_extra)
{
    __shared__ float h_s[BS][HID];
    __shared__ float natt_s[BS][KNUM];
    __shared__ float k2_s[BS][9];
    int t = threadIdx.x;

    {
        int b = t >> 4, j = t & 15;
        const float* pr = &g_pooled[b * CIN];
        const float* wr = &w_net[j * CIN];
        float s = 0.f;
        for (int i = 0; i < CIN; ++i) s += pr[i] * wr[i];
        h_s[b][j] = fmaxf(s, 0.f);
    }
    __syncthreads();

    if (t < BS) {
        float l[KNUM];
        float mx = -1e30f;
        for (int k = 0; k < KNUM; ++k) {
            float s = 0.f;
            for (int j = 0; j < HID; ++j) s += h_s[t][j] * w_nfc[k * HID + j];
            l[k] = s * (1.f / 30.f);
            mx = fmaxf(mx, l[k]);
        }
        float den = 0.f;
        for (int k = 0; k < KNUM; ++k) { l[k] = expf(l[k] - mx); den += l[k]; }
        float inv = 1.f / den;
        for (int k = 0; k < KNUM; ++k) natt_s[t][k] = l[k] * inv;
    }
    if (t >= 64 && t < 64 + BS * 9) {
        int idx = t - 64;
        int b = idx / 9, cd = idx % 9;
        float s = 0.f;
        for (int j = 0; j < HID; ++j) s += h_s[b][j] * w_k2[cd * HID + j];
        k2_s[b][cd] = sigmoidf_(s);
    }
    __syncthreads();

    if (t < BS * 9) {
        int b = t / 9, cd = t % 9;
        float m[9];
#pragma unroll
        for (int s = 0; s < 9; ++s) m[s] = 0.f;
#pragma unroll
        for (int k = 0; k < KNUM; ++k) m[c_perm[k][cd]] += natt_s[b][k];
        float k2v = k2_s[b][cd];
#pragma unroll
        for (int s = 0; s < 9; ++s) g_mix[(b * 9 + cd) * 9 + s] = k2v * m[s];
    }

    for (int idx = t; idx < BS * CIN; idx += blockDim.x) {
        int b = idx >> 8, c = idx & 255;
        float s1 = 0.f, s2 = 0.f;
        for (int j = 0; j < HID; ++j) {
            float hv = h_s[b][j];
            s1 += hv * w_cin[c * HID + j];
            s2 += hv * w_out[c * HID + j];
        }
        g_cinatt[idx] = sigmoidf_(s1);
        g_outatt[idx] = sigmoidf_(s2);
        float bb = natt_s[b][0] * b_base[c];
        for (int k = 1; k < KNUM; ++k) bb += natt_s[b][k] * b_extra[(k - 1) * COUT + c];
        g_aggb[idx] = bb;
    }
}

// ---------------- kernel 3: materialize fused per-sample weights ----------------
__global__ void wfuse_kernel(const float* __restrict__ w_base)
{
    int i = blockIdx.x;
    int b = blockIdx.y;
    int o = threadIdx.x;
    __shared__ float mix_s[81];
    if (o < 81) mix_s[o] = g_mix[b * 81 + o];
    __syncthreads();

    float wb[9];
    const float* wp = &w_base[((size_t)o * CIN + i) * 9];
#pragma unroll
    for (int s = 0; s < 9; ++s) wb[s] = wp[s];
    float sc = g_cinatt[b * CIN + i] * g_outatt[b * COUT + o];
    float* dst = &g_W[(((size_t)(b * CIN + i)) * 9) * COUT + o];
#pragma unroll
    for (int tt = 0; tt < 9; ++tt) {
        float v = 0.f;
#pragma unroll
        for (int s = 0; s < 9; ++s) v += mix_s[tt * 9 + s] * wb[s];
        dst[(size_t)tt * COUT] = sc * v;
    }
}

// ---------------- packed f32x2 / cp.async helpers ----------------
__device__ __forceinline__ unsigned long long ffma2(unsigned long long a,
                                                    unsigned long long b,
                                                    unsigned long long c)
{
    unsigned long long d;
    asm("fma.rn.f32x2 %0, %1, %2, %3;" : "=l"(d) : "l"(a), "l"(b), "l"(c));
    return d;
}
__device__ __forceinline__ unsigned long long bcast2(float x)
{
    unsigned long long d;
    unsigned u = __float_as_uint(x);
    asm("mov.b64 %0, {%1, %2};" : "=l"(d) : "r"(u), "r"(u));
    return d;
}
__device__ __forceinline__ unsigned sptr(const void* p)
{
    return (unsigned)__cvta_generic_to_shared(p);
}
__device__ __forceinline__ void cpA4(unsigned dst, const float* src, int srcsz)
{
    asm volatile("cp.async.ca.shared.global [%0], [%1], 4, %2;"
                 :: "r"(dst), "l"(src), "r"(srcsz));
}
__device__ __forceinline__ void cpA16(unsigned dst, const float* src)
{
    asm volatile("cp.async.ca.shared.global [%0], [%1], 16;"
                 :: "r"(dst), "l"(src));
}

// ---------------- kernel 4: per-sample 3x3 conv, pipelined f32x2 ----------------
// CTA: sample b, 64 output channels, 16x16 spatial tile.
// Thread: 16 oc (8 packed pairs) x 4 consecutive width positions.
#define BKC 4
__global__ __launch_bounds__(256, 2) void conv_kernel(const float* __restrict__ x,
                                                      float* __restrict__ out)
{
    const int b   = blockIdx.z;
    const int ocb = blockIdx.y;
    const int th0 = (blockIdx.x / 5) * 16;
    const int tw0 = (blockIdx.x % 5) * 16;
    const int tid = threadIdx.x;
    const int g   = tid >> 6;
    const int p   = tid & 63;
    const int row = p >> 2;
    const int cg  = (p & 3) << 2;

    __shared__ __align__(16) float xs[2][BKC][18][20];
    __shared__ __align__(16) float ws[2][BKC][9][64];

    unsigned long long acc[8][4];
#pragma unroll
    for (int q = 0; q < 8; ++q)
#pragma unroll
        for (int pos = 0; pos < 4; ++pos) acc[q][pos] = 0ULL;

    const float* xb  = x + (size_t)b * CIN * HWSZ;
    const float* wbp = g_W + (size_t)b * CIN * 9 * COUT + (size_t)ocb * 64;

    // ---- staging (cp.async) for one chunk into buffer `buf` ----
    auto prefetch = [&](int buf, int kc0) {
        // x halo tile: BKC * 18 * 18 scalars, zero-fill out-of-bounds
#pragma unroll 1
        for (int idx = tid; idx < BKC * 324; idx += 256) {
            int kc  = idx / 324;
            int rem = idx - kc * 324;
            int r   = rem / 18;
            int c   = rem - r * 18;
            int gh = th0 - 1 + r, gw = tw0 - 1 + c;
            bool v = ((unsigned)gh < 80u) && ((unsigned)gw < 80u);
            const float* src = v ? &xb[(size_t)(kc0 + kc) * HWSZ + gh * 80 + gw] : xb;
            cpA4(sptr(&xs[buf][kc][r][c]), src, v ? 4 : 0);
        }
        // weights: BKC * 9 * 64 floats as 16B copies
#pragma unroll 1
        for (int idx = tid; idx < BKC * 9 * 16; idx += 256) {
            int kc  = idx / 144;
            int rem = idx - kc * 144;
            int tt  = rem >> 4;
            int o4  = rem & 15;
            cpA16(sptr(&ws[buf][kc][tt][o4 * 4]),
                  &wbp[(size_t)((kc0 + kc) * 9 + tt) * COUT + o4 * 4]);
        }
    };

    const int NCH = CIN / BKC;            // 64 chunks
    prefetch(0, 0);
    asm volatile("cp.async.commit_group;");

#pragma unroll 1
    for (int i = 0; i < NCH; ++i) {
        if (i + 1 < NCH) {
            prefetch((i + 1) & 1, (i + 1) * BKC);
            asm volatile("cp.async.commit_group;");
            asm volatile("cp.async.wait_group 1;");
        } else {
            asm volatile("cp.async.wait_group 0;");
        }
        __syncthreads();

        const int buf = i & 1;
#pragma unroll
        for (int kc = 0; kc < BKC; ++kc) {
#pragma unroll
            for (int tr = 0; tr < 3; ++tr) {
                const float* xp = &xs[buf][kc][row + tr][cg];
                float4 v4 = *reinterpret_cast<const float4*>(xp);
                float2 v2 = *reinterpret_cast<const float2*>(xp + 4);
                unsigned long long xx[6];
                xx[0] = bcast2(v4.x); xx[1] = bcast2(v4.y); xx[2] = bcast2(v4.z);
                xx[3] = bcast2(v4.w); xx[4] = bcast2(v2.x); xx[5] = bcast2(v2.y);
#pragma unroll
                for (int tc = 0; tc < 3; ++tc) {
                    const ulonglong2* wp4 =
                        reinterpret_cast<const ulonglong2*>(&ws[buf][kc][tr * 3 + tc][g * 16]);
                    ulonglong2 wv0 = wp4[0];
                    ulonglong2 wv1 = wp4[1];
                    ulonglong2 wv2 = wp4[2];
                    ulonglong2 wv3 = wp4[3];
                    unsigned long long w2[8] = { wv0.x, wv0.y, wv1.x, wv1.y,
                                                 wv2.x, wv2.y, wv3.x, wv3.y };
#pragma unroll
                    for (int q = 0; q < 8; ++q) {
                        acc[q][0] = ffma2(w2[q], xx[tc + 0], acc[q][0]);
                        acc[q][1] = ffma2(w2[q], xx[tc + 1], acc[q][1]);
                        acc[q][2] = ffma2(w2[q], xx[tc + 2], acc[q][2]);
                        acc[q][3] = ffma2(w2[q], xx[tc + 3], acc[q][3]);
                    }
                }
            }
        }
        __syncthreads();   // protect buf before chunk i+2 prefetch overwrites it
    }

    // epilogue
    const int oc_base = ocb * 64 + g * 16;
    const int hh = th0 + row;
    const int wc = tw0 + cg;
#pragma unroll
    for (int q = 0; q < 8; ++q) {
        int oc_lo = oc_base + 2 * q;
        float blo = g_aggb[b * COUT + oc_lo];
        float bhi = g_aggb[b * COUT + oc_lo + 1];
        float lo[4], hi[4];
#pragma unroll
        for (int pos = 0; pos < 4; ++pos) {
            unsigned l32, h32;
            asm("mov.b64 {%0, %1}, %2;" : "=r"(l32), "=r"(h32) : "l"(acc[q][pos]));
            lo[pos] = __uint_as_float(l32) + blo;
            hi[pos] = __uint_as_float(h32) + bhi;
        }
        float* olo = out + (((size_t)b * COUT + oc_lo) * HH + hh) * WW + wc;
        float* ohi = olo + HWSZ;
        *reinterpret_cast<float4*>(olo) = make_float4(lo[0], lo[1], lo[2], lo[3]);
        *reinterpret_cast<float4*>(ohi) = make_float4(hi[0], hi[1], hi[2], hi[3]);
    }
}

// ---------------- launch ----------------
extern "C" void kernel_launch(void* const* d_in, const int* in_sizes, int n_in,
                              void* d_out, int out_size)
{
    const float* x       = (const float*)d_in[0];
    const float* w_base  = (const float*)d_in[1];
    const float* b_base  = (const float*)d_in[2];
    const float* b_extra = (const float*)d_in[3];
    const float* w_net   = (const float*)d_in[4];
    const float* w_nfc   = (const float*)d_in[5];
    const float* w_cin   = (const float*)d_in[6];
    const float* w_k2    = (const float*)d_in[7];
    const float* w_out   = (const float*)d_in[8];
    float* out = (float*)d_out;

    pool_kernel<<<BS * CIN, 256>>>(x);
    att_kernel<<<1, 256>>>(w_net, w_nfc, w_cin, w_k2, w_out, b_base, b_extra);
    {
        dim3 grid(CIN, BS);
        wfuse_kernel<<<grid, 256>>>(w_base);
    }
    {
        dim3 grid(25, 4, BS);
        conv_kernel<<<grid, 256>>>(x, out);
    }
}

// round 3
// speedup vs baseline: 1.4447x; 1.0015x over previous
#include <cuda_runtime.h>
#include <math.h>

#define BS   16
#define CIN  256
#define COUT 256
#define HH   80
#define WW   80
#define HWSZ 6400
#define HID  16
#define KNUM 5

// ---------------- scratch (static device globals; no allocation) ----------------
__device__ float g_pooled[BS * CIN];
__device__ float g_mix[BS * 9 * 9];          // [b][cd][s]
__device__ float g_cinatt[BS * CIN];
__device__ float g_outatt[BS * COUT];
__device__ float g_aggb[BS * COUT];
__device__ __align__(16) float g_W[(size_t)BS * CIN * 9 * COUT];   // [b][i][tap][o]

// rotation perms: dest -> source flat index (k=0 identity, then 45/90/135/180)
__constant__ int c_perm[KNUM][9] = {
    {0,1,2,3,4,5,6,7,8},
    {3,0,1,6,4,2,7,8,5},
    {6,3,0,7,4,1,8,5,2},
    {7,6,3,8,4,0,5,2,1},
    {8,7,6,5,4,3,2,1,0},
};

__device__ __forceinline__ float sigmoidf_(float z) { return 1.f / (1.f + expf(-z)); }

// ---------------- kernel 1: global average pool ----------------
__global__ void pool_kernel(const float* __restrict__ x)
{
    int bc = blockIdx.x;                      // b*CIN + i
    const float* p = x + (size_t)bc * HWSZ;
    int tid = threadIdx.x;
    float s = 0.f;
    for (int i = tid; i < HWSZ; i += 256) s += p[i];
    __shared__ float sred[256];
    sred[tid] = s;
    __syncthreads();
    for (int st = 128; st > 0; st >>= 1) {
        if (tid < st) sred[tid] += sred[tid + st];
        __syncthreads();
    }
    if (tid == 0) g_pooled[bc] = sred[0] * (1.f / (float)HWSZ);
}

// ---------------- kernel 2: attention heads + mix coefficients + bias ----------------
__global__ void att_kernel(const float* __restrict__ w_net,
                           const float* __restrict__ w_nfc,
                           const float* __restrict__ w_cin,
                           const float* __restrict__ w_k2,
                           const float* __restrict__ w_out,
                           const float* __restrict__ b_base,
                           const float* __restrict__ b_extra)
{
    __shared__ float h_s[BS][HID];
    __shared__ float natt_s[BS][KNUM];
    __shared__ float k2_s[BS][9];
    int t = threadIdx.x;

    {
        int b = t >> 4, j = t & 15;
        const float* pr = &g_pooled[b * CIN];
        const float* wr = &w_net[j * CIN];
        float s = 0.f;
        for (int i = 0; i < CIN; ++i) s += pr[i] * wr[i];
        h_s[b][j] = fmaxf(s, 0.f);
    }
    __syncthreads();

    if (t < BS) {
        float l[KNUM];
        float mx = -1e30f;
        for (int k = 0; k < KNUM; ++k) {
            float s = 0.f;
            for (int j = 0; j < HID; ++j) s += h_s[t][j] * w_nfc[k * HID + j];
            l[k] = s * (1.f / 30.f);
            mx = fmaxf(mx, l[k]);
        }
        float den = 0.f;
        for (int k = 0; k < KNUM; ++k) { l[k] = expf(l[k] - mx); den += l[k]; }
        float inv = 1.f / den;
        for (int k = 0; k < KNUM; ++k) natt_s[t][k] = l[k] * inv;
    }
    if (t >= 64 && t < 64 + BS * 9) {
        int idx = t - 64;
        int b = idx / 9, cd = idx % 9;
        float s = 0.f;
        for (int j = 0; j < HID; ++j) s += h_s[b][j] * w_k2[cd * HID + j];
        k2_s[b][cd] = sigmoidf_(s);
    }
    __syncthreads();

    if (t < BS * 9) {
        int b = t / 9, cd = t % 9;
        float m[9];
#pragma unroll
        for (int s = 0; s < 9; ++s) m[s] = 0.f;
#pragma unroll
        for (int k = 0; k < KNUM; ++k) m[c_perm[k][cd]] += natt_s[b][k];
        float k2v = k2_s[b][cd];
#pragma unroll
        for (int s = 0; s < 9; ++s) g_mix[(b * 9 + cd) * 9 + s] = k2v * m[s];
    }

    for (int idx = t; idx < BS * CIN; idx += blockDim.x) {
        int b = idx >> 8, c = idx & 255;
        float s1 = 0.f, s2 = 0.f;
        for (int j = 0; j < HID; ++j) {
            float hv = h_s[b][j];
            s1 += hv * w_cin[c * HID + j];
            s2 += hv * w_out[c * HID + j];
        }
        g_cinatt[idx] = sigmoidf_(s1);
        g_outatt[idx] = sigmoidf_(s2);
        float bb = natt_s[b][0] * b_base[c];
        for (int k = 1; k < KNUM; ++k) bb += natt_s[b][k] * b_extra[(k - 1) * COUT + c];
        g_aggb[idx] = bb;
    }
}

// ---------------- kernel 3: materialize fused per-sample weights ----------------
__global__ void wfuse_kernel(const float* __restrict__ w_base)
{
    int i = blockIdx.x;
    int b = blockIdx.y;
    int o = threadIdx.x;
    __shared__ float mix_s[81];
    if (o < 81) mix_s[o] = g_mix[b * 81 + o];
    __syncthreads();

    float wb[9];
    const float* wp = &w_base[((size_t)o * CIN + i) * 9];
#pragma unroll
    for (int s = 0; s < 9; ++s) wb[s] = wp[s];
    float sc = g_cinatt[b * CIN + i] * g_outatt[b * COUT + o];
    float* dst = &g_W[(((size_t)(b * CIN + i)) * 9) * COUT + o];
#pragma unroll
    for (int tt = 0; tt < 9; ++tt) {
        float v = 0.f;
#pragma unroll
        for (int s = 0; s < 9; ++s) v += mix_s[tt * 9 + s] * wb[s];
        dst[(size_t)tt * COUT] = sc * v;
    }
}

// ---------------- packed f32x2 / cp.async helpers ----------------
__device__ __forceinline__ unsigned long long ffma2(unsigned long long a,
                                                    unsigned long long b,
                                                    unsigned long long c)
{
    unsigned long long d;
    asm("fma.rn.f32x2 %0, %1, %2, %3;" : "=l"(d) : "l"(a), "l"(b), "l"(c));
    return d;
}
__device__ __forceinline__ unsigned long long bcast2(float x)
{
    unsigned long long d;
    unsigned u = __float_as_uint(x);
    asm("mov.b64 %0, {%1, %2};" : "=l"(d) : "r"(u), "r"(u));
    return d;
}
__device__ __forceinline__ unsigned sptr(const void* p)
{
    return (unsigned)__cvta_generic_to_shared(p);
}
__device__ __forceinline__ void cpA4(unsigned dst, const float* src, int srcsz)
{
    asm volatile("cp.async.ca.shared.global [%0], [%1], 4, %2;"
                 :: "r"(dst), "l"(src), "r"(srcsz));
}
__device__ __forceinline__ void cpA16(unsigned dst, const float* src)
{
    asm volatile("cp.async.ca.shared.global [%0], [%1], 16;"
                 :: "r"(dst), "l"(src));
}

// ---------------- kernel 4: per-sample 3x3 conv, pipelined f32x2 ----------------
// CTA: sample b, 64 output channels, 16x16 spatial tile.
// Thread: 16 oc (8 packed pairs) x 4 consecutive width positions.
#define BKC 4
__global__ __launch_bounds__(256, 2) void conv_kernel(const float* __restrict__ x,
                                                      float* __restrict__ out)
{
    const int b   = blockIdx.z;
    const int ocb = blockIdx.y;
    const int th0 = (blockIdx.x / 5) * 16;
    const int tw0 = (blockIdx.x % 5) * 16;
    const int tid = threadIdx.x;
    const int g   = tid >> 6;
    const int p   = tid & 63;
    const int row = p >> 2;
    const int cg  = (p & 3) << 2;

    __shared__ __align__(16) float xs[2][BKC][18][20];
    __shared__ __align__(16) float ws[2][BKC][9][64];

    unsigned long long acc[8][4];
#pragma unroll
    for (int q = 0; q < 8; ++q)
#pragma unroll
        for (int pos = 0; pos < 4; ++pos) acc[q][pos] = 0ULL;

    const float* xb  = x + (size_t)b * CIN * HWSZ;
    const float* wbp = g_W + (size_t)b * CIN * 9 * COUT + (size_t)ocb * 64;

    // ---- staging (cp.async) for one chunk into buffer `buf` ----
    auto prefetch = [&](int buf, int kc0) {
        // x halo tile: BKC * 18 * 18 scalars, zero-fill out-of-bounds
#pragma unroll 1
        for (int idx = tid; idx < BKC * 324; idx += 256) {
            int kc  = idx / 324;
            int rem = idx - kc * 324;
            int r   = rem / 18;
            int c   = rem - r * 18;
            int gh = th0 - 1 + r, gw = tw0 - 1 + c;
            bool v = ((unsigned)gh < 80u) && ((unsigned)gw < 80u);
            const float* src = v ? &xb[(size_t)(kc0 + kc) * HWSZ + gh * 80 + gw] : xb;
            cpA4(sptr(&xs[buf][kc][r][c]), src, v ? 4 : 0);
        }
        // weights: BKC * 9 * 64 floats as 16B copies
#pragma unroll 1
        for (int idx = tid; idx < BKC * 9 * 16; idx += 256) {
            int kc  = idx / 144;
            int rem = idx - kc * 144;
            int tt  = rem >> 4;
            int o4  = rem & 15;
            cpA16(sptr(&ws[buf][kc][tt][o4 * 4]),
                  &wbp[(size_t)((kc0 + kc) * 9 + tt) * COUT + o4 * 4]);
        }
    };

    const int NCH = CIN / BKC;            // 64 chunks
    prefetch(0, 0);
    asm volatile("cp.async.commit_group;");

#pragma unroll 1
    for (int i = 0; i < NCH; ++i) {
        if (i + 1 < NCH) {
            prefetch((i + 1) & 1, (i + 1) * BKC);
            asm volatile("cp.async.commit_group;");
            asm volatile("cp.async.wait_group 1;");
        } else {
            asm volatile("cp.async.wait_group 0;");
        }
        __syncthreads();

        const int buf = i & 1;
#pragma unroll
        for (int kc = 0; kc < BKC; ++kc) {
#pragma unroll
            for (int tr = 0; tr < 3; ++tr) {
                const float* xp = &xs[buf][kc][row + tr][cg];
                float4 v4 = *reinterpret_cast<const float4*>(xp);
                float2 v2 = *reinterpret_cast<const float2*>(xp + 4);
                unsigned long long xx[6];
                xx[0] = bcast2(v4.x); xx[1] = bcast2(v4.y); xx[2] = bcast2(v4.z);
                xx[3] = bcast2(v4.w); xx[4] = bcast2(v2.x); xx[5] = bcast2(v2.y);
#pragma unroll
                for (int tc = 0; tc < 3; ++tc) {
                    const ulonglong2* wp4 =
                        reinterpret_cast<const ulonglong2*>(&ws[buf][kc][tr * 3 + tc][g * 16]);
                    ulonglong2 wv0 = wp4[0];
                    ulonglong2 wv1 = wp4[1];
                    ulonglong2 wv2 = wp4[2];
                    ulonglong2 wv3 = wp4[3];
                    unsigned long long w2[8] = { wv0.x, wv0.y, wv1.x, wv1.y,
                                                 wv2.x, wv2.y, wv3.x, wv3.y };
#pragma unroll
                    for (int q = 0; q < 8; ++q) {
                        acc[q][0] = ffma2(w2[q], xx[tc + 0], acc[q][0]);
                        acc[q][1] = ffma2(w2[q], xx[tc + 1], acc[q][1]);
                        acc[q][2] = ffma2(w2[q], xx[tc + 2], acc[q][2]);
                        acc[q][3] = ffma2(w2[q], xx[tc + 3], acc[q][3]);
                    }
                }
            }
        }
        __syncthreads();   // protect buf before chunk i+2 prefetch overwrites it
    }

    // epilogue
    const int oc_base = ocb * 64 + g * 16;
    const int hh = th0 + row;
    const int wc = tw0 + cg;
#pragma unroll
    for (int q = 0; q < 8; ++q) {
        int oc_lo = oc_base + 2 * q;
        float blo = g_aggb[b * COUT + oc_lo];
        float bhi = g_aggb[b * COUT + oc_lo + 1];
        float lo[4], hi[4];
#pragma unroll
        for (int pos = 0; pos < 4; ++pos) {
            unsigned l32, h32;
            asm("mov.b64 {%0, %1}, %2;" : "=r"(l32), "=r"(h32) : "l"(acc[q][pos]));
            lo[pos] = __uint_as_float(l32) + blo;
            hi[pos] = __uint_as_float(h32) + bhi;
        }
        float* olo = out + (((size_t)b * COUT + oc_lo) * HH + hh) * WW + wc;
        float* ohi = olo + HWSZ;
        *reinterpret_cast<float4*>(olo) = make_float4(lo[0], lo[1], lo[2], lo[3]);
        *reinterpret_cast<float4*>(ohi) = make_float4(hi[0], hi[1], hi[2], hi[3]);
    }
}

// ---------------- launch ----------------
extern "C" void kernel_launch(void* const* d_in, const int* in_sizes, int n_in,
                              void* d_out, int out_size)
{
    const float* x       = (const float*)d_in[0];
    const float* w_base  = (const float*)d_in[1];
    const float* b_base  = (const float*)d_in[2];
    const float* b_extra = (const float*)d_in[3];
    const float* w_net   = (const float*)d_in[4];
    const float* w_nfc   = (const float*)d_in[5];
    const float* w_cin   = (const float*)d_in[6];
    const float* w_k2    = (const float*)d_in[7];
    const float* w_out   = (const float*)d_in[8];
    float* out = (float*)d_out;

    pool_kernel<<<BS * CIN, 256>>>(x);
    att_kernel<<<1, 256>>>(w_net, w_nfc, w_cin, w_k2, w_out, b_base, b_extra);
    {
        dim3 grid(CIN, BS);
        wfuse_kernel<<<grid, 256>>>(w_base);
    }
    {
        dim3 grid(25, 4, BS);
        conv_kernel<<<grid, 256>>>(x, out);
    }
}

// round 5
// speedup vs baseline: 2.6605x; 1.8416x over previous
#include <cuda_runtime.h>
#include <cuda_bf16.h>
#include <math.h>
#include <stdint.h>

#define BS   16
#define CIN  256
#define COUT 256
#define HH   80
#define WW   80
#define HWSZ 6400
#define HID  16
#define KNUM 5

// padded spatial grid: 82x82 (1-halo), row stride 82
#define QROW 82
#define QP   6724
#define PADQ 512          // slack rows either side of the whole [b][q] range
#define NTILE 256         // GEMM N per CTA (spatial positions)
#define NT    26
#define MTILE 128         // GEMM M per CTA (output channels)
#define KC    64          // cin per chunk
#define SPAN  422         // NTILE + 2*83 halo rows staged per chunk
#define XROWB 144         // smem row pitch bytes (72 bf16) -> conflict-free ldmatrix

// smem layout (bytes)
#define SO_XH     0
#define SO_XL     60768                      // 422*144
#define SO_WH(bf) (121536 + (bf) * 18432)    // 128*144 each
#define SO_WL(bf) (158400 + (bf) * 18432)
#define SMEM_TOTAL 195264

// ---------------- scratch (static device globals; no allocation) ----------------
__device__ float g_pooled[BS * CIN];
__device__ float g_mix[BS * 9 * 9];
__device__ float g_cinatt[BS * CIN];
__device__ float g_outatt[BS * COUT];
__device__ float g_aggb[BS * COUT];

// x in padded HWC bf16 hi/lo: row index = b*QP + q + PADQ, 256 cin per row
__device__ __align__(128) __nv_bfloat16 g_xh[((size_t)BS * QP + 2 * PADQ) * CIN];
__device__ __align__(128) __nv_bfloat16 g_xl[((size_t)BS * QP + 2 * PADQ) * CIN];
// fused per-sample weights bf16 hi/lo: [b][tap][o][i]
__device__ __align__(128) __nv_bfloat16 g_wh[(size_t)BS * 9 * COUT * CIN];
__device__ __align__(128) __nv_bfloat16 g_wl[(size_t)BS * 9 * COUT * CIN];

__constant__ int c_perm[KNUM][9] = {
    {0,1,2,3,4,5,6,7,8},
    {3,0,1,6,4,2,7,8,5},
    {6,3,0,7,4,1,8,5,2},
    {7,6,3,8,4,0,5,2,1},
    {8,7,6,5,4,3,2,1,0},
};

__device__ __forceinline__ float sigmoidf_(float z) { return 1.f / (1.f + expf(-z)); }

// ================= low-level helpers =================
__device__ __forceinline__ uint32_t smem_u32(const void* p)
{
    return (uint32_t)__cvta_generic_to_shared(p);
}
__device__ __forceinline__ void cpA16(uint32_t dst, const void* src)
{
    asm volatile("cp.async.ca.shared.global [%0], [%1], 16;"
                 :: "r"(dst), "l"(src));
}
#define CP_COMMIT() asm volatile("cp.async.commit_group;")
#define CP_WAIT0()  asm volatile("cp.async.wait_group 0;")

#define LDSM4(r, addr)                                                        \
    asm volatile("ldmatrix.sync.aligned.m8n8.x4.shared.b16 {%0,%1,%2,%3}, [%4];" \
                 : "=r"((r)[0]), "=r"((r)[1]), "=r"((r)[2]), "=r"((r)[3])     \
                 : "r"(addr))

#define MMA(d, a, b0, b1)                                                     \
    asm volatile("mma.sync.aligned.m16n8k16.row.col.f32.bf16.bf16.f32 "      \
                 "{%0,%1,%2,%3}, {%4,%5,%6,%7}, {%8,%9}, {%0,%1,%2,%3};"     \
                 : "+f"((d)[0]), "+f"((d)[1]), "+f"((d)[2]), "+f"((d)[3])    \
                 : "r"((a)[0]), "r"((a)[1]), "r"((a)[2]), "r"((a)[3]),       \
                   "r"(b0), "r"(b1))

// ---------------- kernel 1: global average pool ----------------
__global__ void pool_kernel(const float* __restrict__ x)
{
    int bc = blockIdx.x;
    const float* p = x + (size_t)bc * HWSZ;
    int tid = threadIdx.x;
    float s = 0.f;
    for (int i = tid; i < HWSZ; i += 256) s += p[i];
    __shared__ float sred[256];
    sred[tid] = s;
    __syncthreads();
    for (int st = 128; st > 0; st >>= 1) {
        if (tid < st) sred[tid] += sred[tid + st];
        __syncthreads();
    }
    if (tid == 0) g_pooled[bc] = sred[0] * (1.f / (float)HWSZ);
}

// ---------------- kernel 2: attention heads + mix + bias ----------------
__global__ void att_kernel(const float* __restrict__ w_net,
                           const float* __restrict__ w_nfc,
                           const float* __restrict__ w_cin,
                           const float* __restrict__ w_k2,
                           const float* __restrict__ w_out,
                           const float* __restrict__ b_base,
                           const float* __restrict__ b_extra)
{
    __shared__ float h_s[BS][HID];
    __shared__ float natt_s[BS][KNUM];
    __shared__ float k2_s[BS][9];
    int t = threadIdx.x;
    {
        int b = t >> 4, j = t & 15;
        const float* pr = &g_pooled[b * CIN];
        const float* wr = &w_net[j * CIN];
        float s = 0.f;
        for (int i = 0; i < CIN; ++i) s += pr[i] * wr[i];
        h_s[b][j] = fmaxf(s, 0.f);
    }
    __syncthreads();
    if (t < BS) {
        float l[KNUM];
        float mx = -1e30f;
        for (int k = 0; k < KNUM; ++k) {
            float s = 0.f;
            for (int j = 0; j < HID; ++j) s += h_s[t][j] * w_nfc[k * HID + j];
            l[k] = s * (1.f / 30.f);
            mx = fmaxf(mx, l[k]);
        }
        float den = 0.f;
        for (int k = 0; k < KNUM; ++k) { l[k] = expf(l[k] - mx); den += l[k]; }
        float inv = 1.f / den;
        for (int k = 0; k < KNUM; ++k) natt_s[t][k] = l[k] * inv;
    }
    if (t >= 64 && t < 64 + BS * 9) {
        int idx = t - 64;
        int b = idx / 9, cd = idx % 9;
        float s = 0.f;
        for (int j = 0; j < HID; ++j) s += h_s[b][j] * w_k2[cd * HID + j];
        k2_s[b][cd] = sigmoidf_(s);
    }
    __syncthreads();
    if (t < BS * 9) {
        int b = t / 9, cd = t % 9;
        float m[9];
#pragma unroll
        for (int s = 0; s < 9; ++s) m[s] = 0.f;
#pragma unroll
        for (int k = 0; k < KNUM; ++k) m[c_perm[k][cd]] += natt_s[b][k];
        float k2v = k2_s[b][cd];
#pragma unroll
        for (int s = 0; s < 9; ++s) g_mix[(b * 9 + cd) * 9 + s] = k2v * m[s];
    }
    for (int idx = t; idx < BS * CIN; idx += blockDim.x) {
        int b = idx >> 8, c = idx & 255;
        float s1 = 0.f, s2 = 0.f;
        for (int j = 0; j < HID; ++j) {
            float hv = h_s[b][j];
            s1 += hv * w_cin[c * HID + j];
            s2 += hv * w_out[c * HID + j];
        }
        g_cinatt[idx] = sigmoidf_(s1);
        g_outatt[idx] = sigmoidf_(s2);
        float bb = natt_s[b][0] * b_base[c];
        for (int k = 1; k < KNUM; ++k) bb += natt_s[b][k] * b_extra[(k - 1) * COUT + c];
        g_aggb[idx] = bb;
    }
}

// ---------------- kernel 3: fused per-sample weights -> bf16 hi/lo [b][tap][o][i] ----------------
__global__ void wfuse_kernel(const float* __restrict__ w_base)
{
    const int o = blockIdx.x, b = blockIdx.y, i = threadIdx.x;
    __shared__ float mix_s[81];
    if (i < 81) mix_s[i] = g_mix[b * 81 + i];
    __syncthreads();
    float wb[9];
    const float* wp = &w_base[((size_t)o * CIN + i) * 9];
#pragma unroll
    for (int s = 0; s < 9; ++s) wb[s] = wp[s];
    float sc = g_cinatt[b * CIN + i] * g_outatt[b * COUT + o];
#pragma unroll
    for (int tap = 0; tap < 9; ++tap) {
        float v = 0.f;
#pragma unroll
        for (int s = 0; s < 9; ++s) v += mix_s[tap * 9 + s] * wb[s];
        v *= sc;
        __nv_bfloat16 vh = __float2bfloat16(v);
        float vl = v - __bfloat162float(vh);
        size_t off = ((size_t)((b * 9 + tap) * COUT + o)) * CIN + i;
        g_wh[off] = vh;
        g_wl[off] = __float2bfloat16(vl);
    }
}

// ---------------- kernel 4: x -> padded HWC bf16 hi/lo ----------------
__global__ void xcvt_kernel(const float* __restrict__ x)
{
    const int rp  = blockIdx.x;               // padded row 0..81
    const int b   = blockIdx.y;
    const int tid = threadIdx.x;
    const size_t pbase = ((size_t)b * QP + PADQ + (size_t)rp * QROW) * CIN;
    if (rp == 0 || rp == 81) {
        for (int idx = tid; idx < QROW * CIN; idx += 256) {
            g_xh[pbase + idx] = __float2bfloat16(0.f);
            g_xl[pbase + idx] = __float2bfloat16(0.f);
        }
        return;
    }
    const int h = rp - 1;
    __shared__ float sm[64][81];
    for (int i0 = 0; i0 < CIN; i0 += 64) {
        for (int k = tid; k < 64 * 80; k += 256) {
            int i = k / 80, w = k % 80;
            sm[i][w] = x[(((size_t)b * CIN + i0 + i) * HH + h) * WW + w];
        }
        __syncthreads();
        int grp = tid >> 6, il = tid & 63;
        for (int cp = grp; cp < QROW; cp += 4) {
            int w = cp - 1;
            float v = ((unsigned)w < 80u) ? sm[il][w] : 0.f;
            __nv_bfloat16 vh = __float2bfloat16(v);
            float vl = v - __bfloat162float(vh);
            size_t off = pbase + (size_t)cp * CIN + i0 + il;
            g_xh[off] = vh;
            g_xl[off] = __float2bfloat16(vl);
        }
        __syncthreads();
    }
}

// ---------------- kernel 5: HMMA split-bf16 conv GEMM ----------------
// grid (26 spatial tiles, 2 ocb, 16 b), 512 threads = 16 warps (4M x 4N),
// warp tile 32(oc) x 64(q). One X span staged per cin chunk, reused by all
// 9 taps via shifted row bases. W double-buffered cp.async per (tap,chunk).
__global__ __launch_bounds__(512, 1)
void conv_mma_kernel(float* __restrict__ out)
{
    extern __shared__ __align__(128) char smem[];
    const uint32_t sb = smem_u32(smem);
    const int tid  = threadIdx.x;
    const int lane = tid & 31;
    const int wid  = tid >> 5;
    const int b    = blockIdx.z;
    const int ocb  = blockIdx.y;
    const int q0   = QROW + blockIdx.x * NTILE;
    const int qbase = q0 - 83;

    const int m0 = (wid >> 2) * 32;
    const int n0 = (wid & 3) * 64;
    const uint32_t aoff = (uint32_t)((lane & 15) * XROWB + (lane >> 4) * 16);

    const __nv_bfloat16* gxh = g_xh + ((size_t)b * QP + PADQ + qbase) * CIN;
    const __nv_bfloat16* gxl = g_xl + ((size_t)b * QP + PADQ + qbase) * CIN;

    float d[2][8][4];
#pragma unroll
    for (int mt = 0; mt < 2; ++mt)
#pragma unroll
        for (int nt = 0; nt < 8; ++nt)
#pragma unroll
            for (int e = 0; e < 4; ++e) d[mt][nt][e] = 0.f;

    // ---- staging helpers ----
    auto stageX = [&](int kc0) {
#pragma unroll 1
        for (int i = tid; i < SPAN * 8; i += 512) {
            int r = i >> 3, c = i & 7;
            uint32_t dof = (uint32_t)(r * XROWB + c * 16);
            size_t sof = (size_t)r * CIN + kc0 + c * 8;
            cpA16(sb + SO_XH + dof, gxh + sof);
            cpA16(sb + SO_XL + dof, gxl + sof);
        }
    };
    auto stageW = [&](int buf, int tap, int kc0) {
        size_t base = ((size_t)((b * 9 + tap) * COUT + ocb * MTILE)) * CIN + kc0;
#pragma unroll 1
        for (int i = tid; i < MTILE * 8; i += 512) {
            int r = i >> 3, c = i & 7;
            uint32_t dof = (uint32_t)(r * XROWB + c * 16);
            size_t sof = base + (size_t)r * CIN + c * 8;
            cpA16(sb + SO_WH(buf) + dof, g_wh + sof);
            cpA16(sb + SO_WL(buf) + dof, g_wl + sof);
        }
    };

    stageW(0, 0, 0);
    CP_COMMIT();

    int s = 0;
#pragma unroll 1
    for (int ch = 0; ch < 4; ++ch) {
        __syncthreads();                       // previous chunk fully consumed
        stageX(ch * KC);
        CP_COMMIT();
        CP_WAIT0();                            // X + pending W ready
        __syncthreads();

#pragma unroll 1
        for (int tap = 0; tap < 9; ++tap, ++s) {
            if (s + 1 < 36) {
                int ns = s + 1;
                stageW(ns & 1, ns % 9, (ns / 9) * KC);
                CP_COMMIT();
            }
            const int buf = s & 1;
            const int dlt = (tap / 3 - 1) * QROW + (tap % 3) - 1;
            const uint32_t xrow = (uint32_t)(n0 + dlt + 83);
            const uint32_t xh_b = sb + SO_XH + xrow * XROWB + aoff;
            const uint32_t xl_b = sb + SO_XL + xrow * XROWB + aoff;
            const uint32_t wh_b = sb + SO_WH(buf) + (uint32_t)m0 * XROWB + aoff;
            const uint32_t wl_b = sb + SO_WL(buf) + (uint32_t)m0 * XROWB + aoff;

#pragma unroll
            for (int kk = 0; kk < 4; ++kk) {
                const uint32_t ko = kk * 32;
                uint32_t ah[2][4], al[2][4], bb[4][4];
                LDSM4(ah[0], wh_b + ko);
                LDSM4(ah[1], wh_b + 16 * XROWB + ko);
                LDSM4(al[0], wl_b + ko);
                LDSM4(al[1], wl_b + 16 * XROWB + ko);
#pragma unroll
                for (int j = 0; j < 4; ++j) LDSM4(bb[j], xh_b + j * 16 * XROWB + ko);
                // Wh*Xh + Wl*Xh
#pragma unroll
                for (int mt = 0; mt < 2; ++mt)
#pragma unroll
                    for (int j = 0; j < 4; ++j) {
                        MMA(d[mt][2 * j],     ah[mt], bb[j][0], bb[j][2]);
                        MMA(d[mt][2 * j + 1], ah[mt], bb[j][1], bb[j][3]);
                        MMA(d[mt][2 * j],     al[mt], bb[j][0], bb[j][2]);
                        MMA(d[mt][2 * j + 1], al[mt], bb[j][1], bb[j][3]);
                    }
                // Wh*Xl
#pragma unroll
                for (int j = 0; j < 4; ++j) LDSM4(bb[j], xl_b + j * 16 * XROWB + ko);
#pragma unroll
                for (int mt = 0; mt < 2; ++mt)
#pragma unroll
                    for (int j = 0; j < 4; ++j) {
                        MMA(d[mt][2 * j],     ah[mt], bb[j][0], bb[j][2]);
                        MMA(d[mt][2 * j + 1], ah[mt], bb[j][1], bb[j][3]);
                    }
            }

            if (s + 1 < 36) CP_WAIT0();
            __syncthreads();
        }
    }

    // ---- epilogue: predicated stores with bias ----
    const int mbase = ocb * MTILE + m0;
    const int qb = q0 + n0;
#pragma unroll
    for (int mt = 0; mt < 2; ++mt) {
#pragma unroll
        for (int r = 0; r < 2; ++r) {
            const int m = mbase + mt * 16 + (lane >> 2) + r * 8;
            const float bias = g_aggb[b * COUT + m];
            float* ob = out + ((size_t)(b * COUT + m)) * HWSZ;
#pragma unroll
            for (int nt = 0; nt < 8; ++nt) {
                const int q = qb + nt * 8 + (lane & 3) * 2;
#pragma unroll
                for (int e = 0; e < 2; ++e) {
                    const int qq = q + e;
                    const int rq = qq / QROW;
                    const int cq = qq - rq * QROW;
                    if (rq >= 1 && rq <= 80 && cq >= 1 && cq <= 80)
                        ob[(rq - 1) * WW + (cq - 1)] = d[mt][nt][r * 2 + e] + bias;
                }
            }
        }
    }
}

// ---------------- launch ----------------
extern "C" void kernel_launch(void* const* d_in, const int* in_sizes, int n_in,
                              void* d_out, int out_size)
{
    const float* x       = (const float*)d_in[0];
    const float* w_base  = (const float*)d_in[1];
    const float* b_base  = (const float*)d_in[2];
    const float* b_extra = (const float*)d_in[3];
    const float* w_net   = (const float*)d_in[4];
    const float* w_nfc   = (const float*)d_in[5];
    const float* w_cin   = (const float*)d_in[6];
    const float* w_k2    = (const float*)d_in[7];
    const float* w_out   = (const float*)d_in[8];
    float* out = (float*)d_out;

    cudaFuncSetAttribute(conv_mma_kernel,
                         cudaFuncAttributeMaxDynamicSharedMemorySize, SMEM_TOTAL);

    pool_kernel<<<BS * CIN, 256>>>(x);
    att_kernel<<<1, 256>>>(w_net, w_nfc, w_cin, w_k2, w_out, b_base, b_extra);
    {
        dim3 grid(COUT, BS);
        wfuse_kernel<<<grid, 256>>>(w_base);
    }
    {
        dim3 grid(QROW, BS);
        xcvt_kernel<<<grid, 256>>>(x);
    }
    {
        dim3 grid(NT, 2, BS);
        conv_mma_kernel<<<grid, 512, SMEM_TOTAL>>>(out);
    }
}

// round 6
// speedup vs baseline: 2.7568x; 1.0362x over previous
#include <cuda_runtime.h>
#include <cuda_bf16.h>
#include <math.h>
#include <stdint.h>

#define BS   16
#define CIN  256
#define COUT 256
#define HH   80
#define WW   80
#define HWSZ 6400
#define HID  16
#define KNUM 5

// padded spatial grid: 82x82 (1-halo), row stride 82
#define QROW 82
#define QP   6724
#define PADQ 128                 // slack rows either side (halo over/under-run)
#define QTOT (QP + 2 * PADQ)     // 6980
#define NTILE 256                // GEMM N per CTA
#define NT    26
#define MTILE 128                // GEMM M per CTA
#define KC    64                 // cin per chunk
#define SPAN  422                // NTILE + 2*83 halo rows per chunk
#define XROWB 144                // row pitch bytes (72 bf16), in gmem AND smem

// smem layout (bytes)
#define SO_XH     0
#define SO_XL     60768                      // SPAN*144
#define SO_WH(bf) (121536 + (bf) * 18432)
#define SO_WL(bf) (158400 + (bf) * 18432)
#define SO_BAR    195264                     // mbarriers
#define SMEM_TOTAL 195392
#define W_STAGE_B  18432                     // 128*144
#define X_STAGE_B  60768                     // 422*144

// ---------------- scratch ----------------
__device__ float g_pooled[BS * CIN];
__device__ float g_mix[BS * 9 * 9];
__device__ float g_cinatt[BS * CIN];
__device__ float g_outatt[BS * COUT];
__device__ float g_aggb[BS * COUT];

// x padded HWC, chunked cin, 72-elem pitch: [b][chunk][qpad][72]
__device__ __align__(128) __nv_bfloat16 g_xh[(size_t)BS * 4 * QTOT * 72];
__device__ __align__(128) __nv_bfloat16 g_xl[(size_t)BS * 4 * QTOT * 72];
// fused weights: [b][tap][chunk][o][72]
__device__ __align__(128) __nv_bfloat16 g_wh[(size_t)BS * 9 * 4 * COUT * 72];
__device__ __align__(128) __nv_bfloat16 g_wl[(size_t)BS * 9 * 4 * COUT * 72];

__constant__ int c_perm[KNUM][9] = {
    {0,1,2,3,4,5,6,7,8},
    {3,0,1,6,4,2,7,8,5},
    {6,3,0,7,4,1,8,5,2},
    {7,6,3,8,4,0,5,2,1},
    {8,7,6,5,4,3,2,1,0},
};

__device__ __forceinline__ float sigmoidf_(float z) { return 1.f / (1.f + expf(-z)); }

// ================= low-level helpers =================
__device__ __forceinline__ uint32_t smem_u32(const void* p)
{
    return (uint32_t)__cvta_generic_to_shared(p);
}
#define MBARRIER_INIT(addr, cnt) \
    asm volatile("mbarrier.init.shared.b64 [%0], %1;" :: "r"(addr), "r"(cnt) : "memory")
#define MBARRIER_EXPECT_TX(addr, tx) \
    asm volatile("mbarrier.arrive.expect_tx.shared.b64 _, [%0], %1;" :: "r"(addr), "r"(tx) : "memory")
#define MBARRIER_WAIT_PARITY(addr, par) do {                                        \
    uint32_t _m = (addr), _p = (par);                                               \
    asm volatile("{\n\t.reg .pred P1;\n\t"                                          \
        "WL_%=:\n\t"                                                                \
        "mbarrier.try_wait.parity.acquire.cta.shared::cta.b64 P1, [%0], %1, 0x989680;\n\t" \
        "@P1 bra.uni WD_%=;\n\t"                                                    \
        "bra.uni WL_%=;\n\t"                                                        \
        "WD_%=:\n\t}" :: "r"(_m), "r"(_p) : "memory");                              \
} while (0)
#define BULK_G2S(dst, src, bytes, mbar)                                             \
    asm volatile("cp.async.bulk.shared::cta.global.mbarrier::complete_tx::bytes "   \
        "[%0], [%1], %2, [%3];"                                                     \
        :: "r"((uint32_t)(dst)), "l"(src), "r"((uint32_t)(bytes)),                  \
           "r"((uint32_t)(mbar)) : "memory")
#define FENCE_PROXY_ASYNC() asm volatile("fence.proxy.async.shared::cta;" ::: "memory")

#define LDSM4(r, addr)                                                        \
    asm volatile("ldmatrix.sync.aligned.m8n8.x4.shared.b16 {%0,%1,%2,%3}, [%4];" \
                 : "=r"((r)[0]), "=r"((r)[1]), "=r"((r)[2]), "=r"((r)[3])     \
                 : "r"(addr))

#define MMA(d, a, b0, b1)                                                     \
    asm volatile("mma.sync.aligned.m16n8k16.row.col.f32.bf16.bf16.f32 "      \
                 "{%0,%1,%2,%3}, {%4,%5,%6,%7}, {%8,%9}, {%0,%1,%2,%3};"     \
                 : "+f"((d)[0]), "+f"((d)[1]), "+f"((d)[2]), "+f"((d)[3])    \
                 : "r"((a)[0]), "r"((a)[1]), "r"((a)[2]), "r"((a)[3]),       \
                   "r"(b0), "r"(b1))

// ---------------- kernel 1: global average pool ----------------
__global__ void pool_kernel(const float* __restrict__ x)
{
    int bc = blockIdx.x;
    const float* p = x + (size_t)bc * HWSZ;
    int tid = threadIdx.x;
    float s = 0.f;
    for (int i = tid; i < HWSZ; i += 256) s += p[i];
    __shared__ float sred[256];
    sred[tid] = s;
    __syncthreads();
    for (int st = 128; st > 0; st >>= 1) {
        if (tid < st) sred[tid] += sred[tid + st];
        __syncthreads();
    }
    if (tid == 0) g_pooled[bc] = sred[0] * (1.f / (float)HWSZ);
}

// ---------------- kernel 2: attention heads + mix + bias ----------------
__global__ void att_kernel(const float* __restrict__ w_net,
                           const float* __restrict__ w_nfc,
                           const float* __restrict__ w_cin,
                           const float* __restrict__ w_k2,
                           const float* __restrict__ w_out,
                           const float* __restrict__ b_base,
                           const float* __restrict__ b_extra)
{
    __shared__ float h_s[BS][HID];
    __shared__ float natt_s[BS][KNUM];
    __shared__ float k2_s[BS][9];
    int t = threadIdx.x;
    {
        int b = t >> 4, j = t & 15;
        const float* pr = &g_pooled[b * CIN];
        const float* wr = &w_net[j * CIN];
        float s = 0.f;
        for (int i = 0; i < CIN; ++i) s += pr[i] * wr[i];
        h_s[b][j] = fmaxf(s, 0.f);
    }
    __syncthreads();
    if (t < BS) {
        float l[KNUM];
        float mx = -1e30f;
        for (int k = 0; k < KNUM; ++k) {
            float s = 0.f;
            for (int j = 0; j < HID; ++j) s += h_s[t][j] * w_nfc[k * HID + j];
            l[k] = s * (1.f / 30.f);
            mx = fmaxf(mx, l[k]);
        }
        float den = 0.f;
        for (int k = 0; k < KNUM; ++k) { l[k] = expf(l[k] - mx); den += l[k]; }
        float inv = 1.f / den;
        for (int k = 0; k < KNUM; ++k) natt_s[t][k] = l[k] * inv;
    }
    if (t >= 64 && t < 64 + BS * 9) {
        int idx = t - 64;
        int b = idx / 9, cd = idx % 9;
        float s = 0.f;
        for (int j = 0; j < HID; ++j) s += h_s[b][j] * w_k2[cd * HID + j];
        k2_s[b][cd] = sigmoidf_(s);
    }
    __syncthreads();
    if (t < BS * 9) {
        int b = t / 9, cd = t % 9;
        float m[9];
#pragma unroll
        for (int s = 0; s < 9; ++s) m[s] = 0.f;
#pragma unroll
        for (int k = 0; k < KNUM; ++k) m[c_perm[k][cd]] += natt_s[b][k];
        float k2v = k2_s[b][cd];
#pragma unroll
        for (int s = 0; s < 9; ++s) g_mix[(b * 9 + cd) * 9 + s] = k2v * m[s];
    }
    for (int idx = t; idx < BS * CIN; idx += blockDim.x) {
        int b = idx >> 8, c = idx & 255;
        float s1 = 0.f, s2 = 0.f;
        for (int j = 0; j < HID; ++j) {
            float hv = h_s[b][j];
            s1 += hv * w_cin[c * HID + j];
            s2 += hv * w_out[c * HID + j];
        }
        g_cinatt[idx] = sigmoidf_(s1);
        g_outatt[idx] = sigmoidf_(s2);
        float bb = natt_s[b][0] * b_base[c];
        for (int k = 1; k < KNUM; ++k) bb += natt_s[b][k] * b_extra[(k - 1) * COUT + c];
        g_aggb[idx] = bb;
    }
}

// ---------------- kernel 3: fused weights -> bf16 hi/lo [b][tap][chunk][o][72] ----------------
__global__ void wfuse_kernel(const float* __restrict__ w_base)
{
    const int o = blockIdx.x, b = blockIdx.y, i = threadIdx.x;
    const int chunk = i >> 6, il = i & 63;
    __shared__ float mix_s[81];
    if (i < 81) mix_s[i] = g_mix[b * 81 + i];
    __syncthreads();
    float wb[9];
    const float* wp = &w_base[((size_t)o * CIN + i) * 9];
#pragma unroll
    for (int s = 0; s < 9; ++s) wb[s] = wp[s];
    float sc = g_cinatt[b * CIN + i] * g_outatt[b * COUT + o];
#pragma unroll
    for (int tap = 0; tap < 9; ++tap) {
        float v = 0.f;
#pragma unroll
        for (int s = 0; s < 9; ++s) v += mix_s[tap * 9 + s] * wb[s];
        v *= sc;
        __nv_bfloat16 vh = __float2bfloat16(v);
        float vl = v - __bfloat162float(vh);
        size_t off = ((((size_t)(b * 9 + tap) * 4 + chunk) * COUT + o) * 72) + il;
        g_wh[off] = vh;
        g_wl[off] = __float2bfloat16(vl);
    }
}

// ---------------- kernel 4: x -> padded chunked HWC bf16 hi/lo ----------------
__global__ void xcvt_kernel(const float* __restrict__ x)
{
    const int rp  = blockIdx.x;               // 0..81 rows, 82/83 slack-zero blocks
    const int b   = blockIdx.y;
    const int tid = threadIdx.x;

    if (rp >= QROW) {                         // zero halo slack (cols 0..63 only)
        const size_t r0 = (rp == QROW) ? 0 : (size_t)(PADQ + QP);
        for (int idx = tid; idx < 4 * PADQ * 64; idx += 256) {
            int chunk = idx / (PADQ * 64);
            int rem   = idx - chunk * PADQ * 64;
            int r     = rem >> 6, c = rem & 63;
            size_t off = (((size_t)(b * 4 + chunk) * QTOT + r0 + r) * 72) + c;
            g_xh[off] = __float2bfloat16(0.f);
            g_xl[off] = __float2bfloat16(0.f);
        }
        return;
    }

    if (rp == 0 || rp == 81) {                // zero grid border rows
        for (int idx = tid; idx < 4 * QROW * 64; idx += 256) {
            int chunk = idx / (QROW * 64);
            int rem   = idx - chunk * QROW * 64;
            int cp    = rem >> 6, c = rem & 63;
            size_t off = (((size_t)(b * 4 + chunk) * QTOT + PADQ + (size_t)rp * QROW + cp) * 72) + c;
            g_xh[off] = __float2bfloat16(0.f);
            g_xl[off] = __float2bfloat16(0.f);
        }
        return;
    }

    const int h = rp - 1;
    __shared__ float sm[64][81];
    for (int chunk = 0; chunk < 4; ++chunk) {
        const int i0 = chunk * 64;
        for (int k = tid; k < 64 * 80; k += 256) {
            int i = k / 80, w = k % 80;
            sm[i][w] = x[(((size_t)b * CIN + i0 + i) * HH + h) * WW + w];
        }
        __syncthreads();
        int grp = tid >> 6, il = tid & 63;
        const size_t rbase = ((size_t)(b * 4 + chunk) * QTOT + PADQ + (size_t)rp * QROW) * 72;
        for (int cp = grp; cp < QROW; cp += 4) {
            int w = cp - 1;
            float v = ((unsigned)w < 80u) ? sm[il][w] : 0.f;
            __nv_bfloat16 vh = __float2bfloat16(v);
            float vl = v - __bfloat162float(vh);
            size_t off = rbase + (size_t)cp * 72 + il;
            g_xh[off] = vh;
            g_xl[off] = __float2bfloat16(vl);
        }
        __syncthreads();
    }
}

// ---------------- kernel 5: HMMA split-bf16 conv GEMM, bulk-copy staging ----------------
__global__ __launch_bounds__(512, 1)
void conv_mma_kernel(float* __restrict__ out)
{
    extern __shared__ __align__(128) char smem[];
    const uint32_t sb = smem_u32(smem);
    const int tid  = threadIdx.x;
    const int lane = tid & 31;
    const int wid  = tid >> 5;
    const int b    = blockIdx.z;
    const int ocb  = blockIdx.y;
    const int q0   = QROW + blockIdx.x * NTILE;
    const int qbase = q0 - 83;

    const int m0 = (wid >> 2) * 32;
    const int n0 = (wid & 3) * 64;
    const uint32_t aoff = (uint32_t)((lane & 15) * XROWB + (lane >> 4) * 16);

    const uint32_t mb_w0 = sb + SO_BAR;
    const uint32_t mb_w1 = sb + SO_BAR + 8;
    const uint32_t mb_x  = sb + SO_BAR + 16;

    if (tid == 0) {
        MBARRIER_INIT(mb_w0, 1);
        MBARRIER_INIT(mb_w1, 1);
        MBARRIER_INIT(mb_x, 1);
        FENCE_PROXY_ASYNC();
    }

    float d[2][8][4];
#pragma unroll
    for (int mt = 0; mt < 2; ++mt)
#pragma unroll
        for (int nt = 0; nt < 8; ++nt)
#pragma unroll
            for (int e = 0; e < 4; ++e) d[mt][nt][e] = 0.f;

    __syncthreads();

    // ---- producer helpers (single thread) ----
    auto issueW = [&](int s) {
        const int tap = s % 9, ch = s / 9, buf = s & 1;
        const uint32_t mb = buf ? mb_w1 : mb_w0;
        const size_t base = (((size_t)(b * 9 + tap) * 4 + ch) * COUT + (size_t)ocb * MTILE) * 72;
        MBARRIER_EXPECT_TX(mb, 2 * W_STAGE_B);
        BULK_G2S(sb + SO_WH(buf), (const char*)g_wh + base * 2, W_STAGE_B, mb);
        BULK_G2S(sb + SO_WL(buf), (const char*)g_wl + base * 2, W_STAGE_B, mb);
    };
    auto issueX = [&](int ch) {
        const size_t base = ((size_t)(b * 4 + ch) * QTOT + PADQ + qbase) * 72;
        MBARRIER_EXPECT_TX(mb_x, 2 * X_STAGE_B);
        BULK_G2S(sb + SO_XH, (const char*)g_xh + base * 2, X_STAGE_B, mb_x);
        BULK_G2S(sb + SO_XL, (const char*)g_xl + base * 2, X_STAGE_B, mb_x);
    };

    if (tid == 0) { issueW(0); issueW(1); }

    int s = 0;
#pragma unroll 1
    for (int ch = 0; ch < 4; ++ch) {
        if (tid == 0) issueX(ch);             // X buffer free (chunk-end sync)
        MBARRIER_WAIT_PARITY(mb_x, ch & 1);

#pragma unroll 1
        for (int tap = 0; tap < 9; ++tap, ++s) {
            const int buf = s & 1;
            MBARRIER_WAIT_PARITY(buf ? mb_w1 : mb_w0, (s >> 1) & 1);

            const int dlt = (tap / 3 - 1) * QROW + (tap % 3) - 1;
            const uint32_t xrow = (uint32_t)(n0 + dlt + 83);
            const uint32_t xh_b = sb + SO_XH + xrow * XROWB + aoff;
            const uint32_t xl_b = sb + SO_XL + xrow * XROWB + aoff;
            const uint32_t wh_b = sb + SO_WH(buf) + (uint32_t)m0 * XROWB + aoff;
            const uint32_t wl_b = sb + SO_WL(buf) + (uint32_t)m0 * XROWB + aoff;

#pragma unroll
            for (int kk = 0; kk < 4; ++kk) {
                const uint32_t ko = kk * 32;
                uint32_t ah[2][4], al[2][4], bb[4][4];
                LDSM4(ah[0], wh_b + ko);
                LDSM4(ah[1], wh_b + 16 * XROWB + ko);
                LDSM4(al[0], wl_b + ko);
                LDSM4(al[1], wl_b + 16 * XROWB + ko);
#pragma unroll
                for (int j = 0; j < 4; ++j) LDSM4(bb[j], xh_b + j * 16 * XROWB + ko);
#pragma unroll
                for (int mt = 0; mt < 2; ++mt)
#pragma unroll
                    for (int j = 0; j < 4; ++j) {
                        MMA(d[mt][2 * j],     ah[mt], bb[j][0], bb[j][2]);
                        MMA(d[mt][2 * j + 1], ah[mt], bb[j][1], bb[j][3]);
                        MMA(d[mt][2 * j],     al[mt], bb[j][0], bb[j][2]);
                        MMA(d[mt][2 * j + 1], al[mt], bb[j][1], bb[j][3]);
                    }
#pragma unroll
                for (int j = 0; j < 4; ++j) LDSM4(bb[j], xl_b + j * 16 * XROWB + ko);
#pragma unroll
                for (int mt = 0; mt < 2; ++mt)
#pragma unroll
                    for (int j = 0; j < 4; ++j) {
                        MMA(d[mt][2 * j],     ah[mt], bb[j][0], bb[j][2]);
                        MMA(d[mt][2 * j + 1], ah[mt], bb[j][1], bb[j][3]);
                    }
            }

            __syncthreads();                  // all warps done with W[buf] (and X at tap 8)
            if (tid == 0) {
                FENCE_PROXY_ASYNC();          // order generic reads before async reuse
                if (s + 2 < 36) issueW(s + 2);
            }
        }
    }

    // ---- epilogue: predicated stores with bias ----
    const int mbase = ocb * MTILE + m0;
    const int qb = q0 + n0;
#pragma unroll
    for (int mt = 0; mt < 2; ++mt) {
#pragma unroll
        for (int r = 0; r < 2; ++r) {
            const int m = mbase + mt * 16 + (lane >> 2) + r * 8;
            const float bias = g_aggb[b * COUT + m];
            float* ob = out + ((size_t)(b * COUT + m)) * HWSZ;
#pragma unroll
            for (int nt = 0; nt < 8; ++nt) {
                const int q = qb + nt * 8 + (lane & 3) * 2;
#pragma unroll
                for (int e = 0; e < 2; ++e) {
                    const int qq = q + e;
                    const int rq = qq / QROW;
                    const int cq = qq - rq * QROW;
                    if (rq >= 1 && rq <= 80 && cq >= 1 && cq <= 80)
                        ob[(rq - 1) * WW + (cq - 1)] = d[mt][nt][r * 2 + e] + bias;
                }
            }
        }
    }
}

// ---------------- launch ----------------
extern "C" void kernel_launch(void* const* d_in, const int* in_sizes, int n_in,
                              void* d_out, int out_size)
{
    const float* x       = (const float*)d_in[0];
    const float* w_base  = (const float*)d_in[1];
    const float* b_base  = (const float*)d_in[2];
    const float* b_extra = (const float*)d_in[3];
    const float* w_net   = (const float*)d_in[4];
    const float* w_nfc   = (const float*)d_in[5];
    const float* w_cin   = (const float*)d_in[6];
    const float* w_k2    = (const float*)d_in[7];
    const float* w_out   = (const float*)d_in[8];
    float* out = (float*)d_out;

    cudaFuncSetAttribute(conv_mma_kernel,
                         cudaFuncAttributeMaxDynamicSharedMemorySize, SMEM_TOTAL);

    pool_kernel<<<BS * CIN, 256>>>(x);
    att_kernel<<<1, 256>>>(w_net, w_nfc, w_cin, w_k2, w_out, b_base, b_extra);
    {
        dim3 grid(COUT, BS);
        wfuse_kernel<<<grid, 256>>>(w_base);
    }
    {
        dim3 grid(QROW + 2, BS);
        xcvt_kernel<<<grid, 256>>>(x);
    }
    {
        dim3 grid(NT, 2, BS);
        conv_mma_kernel<<<grid, 512, SMEM_TOTAL>>>(out);
    }
}